// round 15
// baseline (speedup 1.0000x reference)
#include <cuda_runtime.h>
#include <cuda_fp16.h>
#include <math.h>
#include <stdint.h>

// Problem constants
#define B_    2048
#define NB_   64
#define NS_   16
#define BOX_  12
#define SYM_  8
#define F_    512
#define H_    1024

#define KC    64          // K per chunk (in halves)
#define KROW  72          // halves per smem row (64 + 8 pad) -> 144B, conflict-free
#define NTHREADS 256
#define STAGES 2
#define KSYM  64          // symmetry operands padded K 8 -> 64

// ---------------------------------------------------------------------------
// Persistent scratch: fp16 hi/lo pairs for every GEMM operand.
// ---------------------------------------------------------------------------
__device__ __align__(16) __half g_boxes_hi[(size_t)B_ * NB_ * F_];
__device__ __align__(16) __half g_boxes_lo[(size_t)B_ * NB_ * F_];
__device__ __align__(16) __half g_h_hi[(size_t)B_ * H_];
__device__ __align__(16) __half g_h_lo[(size_t)B_ * H_];
__device__ __align__(16) __half g_acc_hi[(size_t)B_ * F_];
__device__ __align__(16) __half g_acc_lo[(size_t)B_ * F_];
__device__ __align__(16) __half g_Wl_hi[H_ * F_],  g_Wl_lo[H_ * F_];
__device__ __align__(16) __half g_Wr_hi[H_ * F_],  g_Wr_lo[H_ * F_];
__device__ __align__(16) __half g_Ws_hi[F_ * H_],  g_Ws_lo[F_ * H_];
__device__ __align__(16) __half g_Sl_hi[H_ * F_],  g_Sl_lo[H_ * F_];
__device__ __align__(16) __half g_Ss_hi[F_ * H_],  g_Ss_lo[F_ * H_];
__device__ __align__(16) __half g_Srp_hi[H_ * KSYM], g_Srp_lo[H_ * KSYM];
__device__ __align__(16) __half g_sym_hi[(size_t)B_ * NS_ * KSYM];
__device__ __align__(16) __half g_sym_lo[(size_t)B_ * NS_ * KSYM];

// ---------------------------------------------------------------------------
// helpers
// ---------------------------------------------------------------------------
__device__ __forceinline__ void split1(float x, __half& h, __half& l) {
    h = __float2half_rn(x);
    l = __float2half_rn(x - __half2float(h));
}

__device__ __forceinline__ uint32_t smem_u32_of(const void* p) {
    uint32_t a;
    asm("{ .reg .u64 t; cvta.to.shared.u64 t, %1; cvt.u32.u64 %0, t; }"
        : "=r"(a) : "l"(p));
    return a;
}

#define CP_ASYNC16(d, s) \
    asm volatile("cp.async.cg.shared.global [%0], [%1], 16;" :: "r"(d), "l"(s))
#define CP_COMMIT() asm volatile("cp.async.commit_group;" ::: "memory")
#define CP_WAIT1()  asm volatile("cp.async.wait_group 1;" ::: "memory")
#define CP_WAIT0()  asm volatile("cp.async.wait_group 0;" ::: "memory")

__device__ __forceinline__ void ldsm4(uint32_t* r, uint32_t a) {
    asm volatile("ldmatrix.sync.aligned.m8n8.x4.shared.b16 {%0,%1,%2,%3}, [%4];"
                 : "=r"(r[0]), "=r"(r[1]), "=r"(r[2]), "=r"(r[3]) : "r"(a));
}

__device__ __forceinline__ void mma16816_f32(float* d, const uint32_t* a,
                                             uint32_t b0, uint32_t b1)
{
    asm volatile(
        "mma.sync.aligned.m16n8k16.row.col.f32.f16.f16.f32 "
        "{%0,%1,%2,%3}, {%4,%5,%6,%7}, {%8,%9}, {%0,%1,%2,%3};"
        : "+f"(d[0]), "+f"(d[1]), "+f"(d[2]), "+f"(d[3])
        : "r"(a[0]), "r"(a[1]), "r"(a[2]), "r"(a[3]), "r"(b0), "r"(b1));
}

__device__ __forceinline__ void mma16816_f16(uint32_t* d, const uint32_t* a,
                                             uint32_t b0, uint32_t b1)
{
    asm volatile(
        "mma.sync.aligned.m16n8k16.row.col.f16.f16.f16.f16 "
        "{%0,%1}, {%2,%3,%4,%5}, {%6,%7}, {%0,%1};"
        : "+r"(d[0]), "+r"(d[1])
        : "r"(a[0]), "r"(a[1]), "r"(a[2]), "r"(a[3]), "r"(b0), "r"(b1));
}

// ---------------------------------------------------------------------------
// prep kernels
// ---------------------------------------------------------------------------
#define WN_ (H_ * F_)
__global__ void split_weights(const float* __restrict__ Wl, const float* __restrict__ Wr,
                              const float* __restrict__ Ws, const float* __restrict__ Sl,
                              const float* __restrict__ Ss)
{
    int i = blockIdx.x * 256 + threadIdx.x;
    int seg = i / WN_;
    int j   = i - seg * WN_;
    const float* src;
    __half *hi, *lo;
    switch (seg) {
        case 0: src = Wl; hi = g_Wl_hi; lo = g_Wl_lo; break;
        case 1: src = Wr; hi = g_Wr_hi; lo = g_Wr_lo; break;
        case 2: src = Ws; hi = g_Ws_hi; lo = g_Ws_lo; break;
        case 3: src = Sl; hi = g_Sl_hi; lo = g_Sl_lo; break;
        default: src = Ss; hi = g_Ss_hi; lo = g_Ss_lo; break;
    }
    __half h, l; split1(src[j], h, l);
    hi[j] = h; lo[j] = l;
}

__global__ void split_pads(const float* __restrict__ Sr, const float* __restrict__ sym)
{
    int i = blockIdx.x * 256 + threadIdx.x;
    const int nsr = H_ * KSYM;
    if (i < nsr) {
        int r = i / KSYM, c = i - r * KSYM;
        float x = (c < SYM_) ? Sr[r * SYM_ + c] : 0.f;
        __half h, l; split1(x, h, l);
        g_Srp_hi[i] = h; g_Srp_lo[i] = l;
    } else {
        int k = i - nsr;
        if (k < B_ * NS_ * KSYM) {
            int r = k / KSYM, c = k - r * KSYM;
            float x = (c < SYM_) ? sym[r * SYM_ + c] : 0.f;
            __half h, l; split1(x, h, l);
            g_sym_hi[k] = h; g_sym_lo[k] = l;
        }
    }
}

__global__ void boxes_kernel(const float* __restrict__ in,
                             const float* __restrict__ Wb,
                             const float* __restrict__ bb,
                             __half* __restrict__ out_hi,
                             __half* __restrict__ out_lo)
{
    __shared__ float sW[F_ * BOX_];
    __shared__ float sb[F_];
    __shared__ float sin_[32 * BOX_];
    int tid = threadIdx.x;
    for (int i = tid; i < F_ * BOX_; i += 256) sW[i] = Wb[i];
    for (int i = tid; i < F_; i += 256)        sb[i] = bb[i];
    size_t rowbase = (size_t)blockIdx.x * 32;
    for (int i = tid; i < 32 * BOX_; i += 256) sin_[i] = in[rowbase * BOX_ + i];
    __syncthreads();
    for (int idx = tid; idx < 32 * F_; idx += 256) {
        int r = idx >> 9;
        int c = idx & (F_ - 1);
        float s = sb[c];
        #pragma unroll
        for (int j = 0; j < BOX_; j++)
            s = fmaf(sin_[r * BOX_ + j], sW[c * BOX_ + j], s);
        float t = tanhf(s);
        __half h, l; split1(t, h, l);
        out_hi[(rowbase + r) * F_ + c] = h;
        out_lo[(rowbase + r) * F_ + c] = l;
    }
}

// ---------------------------------------------------------------------------
// async copy of R x KC-half tile into smem [R][KROW], 256 threads
// ---------------------------------------------------------------------------
template<int R>
__device__ __forceinline__ void copy_tile(const __half* __restrict__ g, int ldh,
                                          uint32_t sdst, int tid)
{
    constexpr int SEGS = R * 8;
    #pragma unroll
    for (int j = 0; j < SEGS / NTHREADS; j++) {
        int i = tid + NTHREADS * j;
        int row = i >> 3;
        int seg = i & 7;
        CP_ASYNC16(sdst + row * (KROW * 2) + seg * 16,
                   g + (size_t)row * ldh + seg * 8);
    }
}

// ---------------------------------------------------------------------------
// Dual-operand GEMM, fp16 hi/lo 3-pass (hi*hi f32acc, cross shared f16acc).
// BM=64, BN in {128,64}; 256 threads = 8 warps (2m x 4n), warp tile 32x(BN/4).
// cp.async 2-STAGE ring sized for 2 CTAs/SM co-residency (bubble overlap).
// K multiples of 64. Epilogue: bias + tanh -> fp32 or hi/lo halves.
// ---------------------------------------------------------------------------
template<int BN>
__global__ void __launch_bounds__(NTHREADS, 2)
gemm_async(const __half* __restrict__ A1h, const __half* __restrict__ A1l, int lda1,
           const __half* __restrict__ W1h, const __half* __restrict__ W1l, int ldw1, int K1,
           const __half* __restrict__ A2h, const __half* __restrict__ A2l, int lda2,
           const __half* __restrict__ W2h, const __half* __restrict__ W2l, int ldw2, int K2,
           const float* __restrict__ bias1, const float* __restrict__ bias2,
           float* __restrict__ Cf, __half* __restrict__ Chi, __half* __restrict__ Clo,
           int N)
{
    constexpr int BM = 64;
    constexpr int NWARP = BN / 4;               // cols per warp: 32 or 16
    constexpr int NFRAG = NWARP / 8;            // 4 or 2
    constexpr int SA_B = BM * (KROW * 2);       // 18432 bytes
    constexpr int SB_B = BN * (KROW * 2);       // 36864 or 18432
    constexpr int STAGE_B = 2 * SA_B + 2 * SB_B;

    extern __shared__ __align__(16) char smem[];
    const uint32_t smem_u = smem_u32_of(smem);

    const int tid  = threadIdx.x;
    const int wid  = tid >> 5;
    const int lane = tid & 31;
    const int wm   = wid & 1;                   // 2 m-blocks of 32
    const int wn   = wid >> 1;                  // 4 n-blocks of NWARP
    const int row0 = blockIdx.y * BM;
    const int col0 = blockIdx.x * BN;
    const int g    = lane >> 2;
    const int c2   = (lane & 3) * 2;

    float    acc32[2][NFRAG][4];
    uint32_t acc16[2][NFRAG][2];
    #pragma unroll
    for (int mf = 0; mf < 2; mf++)
        #pragma unroll
        for (int nf = 0; nf < NFRAG; nf++) {
            #pragma unroll
            for (int q = 0; q < 4; q++) acc32[mf][nf][q] = 0.f;
            acc16[mf][nf][0] = 0u; acc16[mf][nf][1] = 0u;
        }

    const int n1  = K1 / KC;
    const int n2  = (A2h != nullptr) ? (K2 / KC) : 0;
    const int nch = n1 + n2;

    auto issue = [&](int c) {
        uint32_t sb = smem_u + (uint32_t)(c & 1) * STAGE_B;
        const __half *Ah_, *Al_, *Wh_, *Wl_;
        int lda, ldw, k0;
        if (c < n1) { Ah_ = A1h; Al_ = A1l; Wh_ = W1h; Wl_ = W1l;
                      lda = lda1; ldw = ldw1; k0 = c * KC; }
        else        { Ah_ = A2h; Al_ = A2l; Wh_ = W2h; Wl_ = W2l;
                      lda = lda2; ldw = ldw2; k0 = (c - n1) * KC; }
        copy_tile<BM>(Ah_ + (size_t)row0 * lda + k0, lda, sb, tid);
        copy_tile<BM>(Al_ + (size_t)row0 * lda + k0, lda, sb + SA_B, tid);
        copy_tile<BN>(Wh_ + (size_t)col0 * ldw + k0, ldw, sb + 2 * SA_B, tid);
        copy_tile<BN>(Wl_ + (size_t)col0 * ldw + k0, ldw, sb + 2 * SA_B + SB_B, tid);
        CP_COMMIT();
    };

    // prologue: fill both stages
    issue(0);
    if (nch > 1) issue(1);

    for (int c = 0; c < nch; c++) {
        if (c + 1 < nch) { CP_WAIT1(); } else { CP_WAIT0(); }
        __syncthreads();

        const uint32_t sb = smem_u + (uint32_t)(c & 1) * STAGE_B;
        const uint32_t aAhi = sb;
        const uint32_t aAlo = sb + SA_B;
        const uint32_t aBhi = sb + 2 * SA_B;
        const uint32_t aBlo = sb + 2 * SA_B + SB_B;

        #pragma unroll
        for (int kf = 0; kf < 4; kf++) {
            uint32_t Af[2][4], Alf[2][4];
            const int aoff = ((wm * 32 + (lane & 15)) * KROW
                              + kf * 16 + (lane >> 4) * 8) * 2;
            #pragma unroll
            for (int mf = 0; mf < 2; mf++) {
                ldsm4(Af[mf],  aAhi + aoff + mf * 16 * KROW * 2);
                ldsm4(Alf[mf], aAlo + aoff + mf * 16 * KROW * 2);
            }
            const int boff = ((wn * NWARP + (lane >> 4) * 8 + (lane & 7)) * KROW
                              + kf * 16 + ((lane >> 3) & 1) * 8) * 2;
            #pragma unroll
            for (int nfp = 0; nfp < NFRAG / 2; nfp++) {
                uint32_t Bh[4], Bl[4];
                ldsm4(Bh, aBhi + boff + nfp * 16 * KROW * 2);
                ldsm4(Bl, aBlo + boff + nfp * 16 * KROW * 2);
                #pragma unroll
                for (int mf = 0; mf < 2; mf++) {
                    mma16816_f32(acc32[mf][2 * nfp],     Af[mf],  Bh[0], Bh[1]);
                    mma16816_f32(acc32[mf][2 * nfp + 1], Af[mf],  Bh[2], Bh[3]);
                    mma16816_f16(acc16[mf][2 * nfp],     Af[mf],  Bl[0], Bl[1]);
                    mma16816_f16(acc16[mf][2 * nfp],     Alf[mf], Bh[0], Bh[1]);
                    mma16816_f16(acc16[mf][2 * nfp + 1], Af[mf],  Bl[2], Bl[3]);
                    mma16816_f16(acc16[mf][2 * nfp + 1], Alf[mf], Bh[2], Bh[3]);
                }
            }
        }

        // all warps done reading stage (c&1); safe to overwrite with chunk c+2
        __syncthreads();
        if (c + 2 < nch) issue(c + 2);
    }

    // Epilogue: merge f16 cross-sums into f32, bias + tanh
    #pragma unroll
    for (int mf = 0; mf < 2; mf++) {
        const int r = row0 + wm * 32 + mf * 16 + g;
        #pragma unroll
        for (int nf = 0; nf < NFRAG; nf++) {
            const int cc = col0 + wn * NWARP + nf * 8 + c2;
            __half2 x0 = *reinterpret_cast<__half2*>(&acc16[mf][nf][0]);
            __half2 x1 = *reinterpret_cast<__half2*>(&acc16[mf][nf][1]);
            float b0 = bias1[cc + 0] + (bias2 ? bias2[cc + 0] : 0.f);
            float b1 = bias1[cc + 1] + (bias2 ? bias2[cc + 1] : 0.f);
            float t00 = tanhf(acc32[mf][nf][0] + __low2float(x0)  + b0);
            float t01 = tanhf(acc32[mf][nf][1] + __high2float(x0) + b1);
            float t10 = tanhf(acc32[mf][nf][2] + __low2float(x1)  + b0);
            float t11 = tanhf(acc32[mf][nf][3] + __high2float(x1) + b1);
            if (Cf) {
                *reinterpret_cast<float2*>(Cf + (size_t)r * N + cc)       = make_float2(t00, t01);
                *reinterpret_cast<float2*>(Cf + (size_t)(r + 8) * N + cc) = make_float2(t10, t11);
            } else {
                __half h00, l00, h01, l01, h10, l10, h11, l11;
                split1(t00, h00, l00); split1(t01, h01, l01);
                split1(t10, h10, l10); split1(t11, h11, l11);
                *reinterpret_cast<__half2*>(Chi + (size_t)r * N + cc)       = __halves2half2(h00, h01);
                *reinterpret_cast<__half2*>(Clo + (size_t)r * N + cc)       = __halves2half2(l00, l01);
                *reinterpret_cast<__half2*>(Chi + (size_t)(r + 8) * N + cc) = __halves2half2(h10, h11);
                *reinterpret_cast<__half2*>(Clo + (size_t)(r + 8) * N + cc) = __halves2half2(l10, l11);
            }
        }
    }
}

// ---------------------------------------------------------------------------
// kernel_launch: op sequence constant = [0,0,1] + [0,1]*62 + [2]*16
// Launch order: 0 split_weights, 1 split_pads, 2 boxes, 3.. GEMMs
// (ncu -s 5 -c 1 profiles a steady-state gemm<128>).
// ---------------------------------------------------------------------------
extern "C" void kernel_launch(void* const* d_in, const int* in_sizes, int n_in,
                              void* d_out, int out_size)
{
    const float* inputStacks    = (const float*)d_in[0];
    const float* symmetryStacks = (const float*)d_in[1];
    const float* Wb  = (const float*)d_in[3];
    const float* bb  = (const float*)d_in[4];
    const float* Wl  = (const float*)d_in[5];
    const float* bl  = (const float*)d_in[6];
    const float* Wr  = (const float*)d_in[7];
    const float* Ws  = (const float*)d_in[8];
    const float* bs  = (const float*)d_in[9];
    const float* Sl  = (const float*)d_in[10];
    const float* sbl = (const float*)d_in[11];
    const float* Sr  = (const float*)d_in[12];
    const float* sbr = (const float*)d_in[13];
    const float* Ss  = (const float*)d_in[14];
    const float* sbs = (const float*)d_in[15];
    float* out = (float*)d_out;

    __half *bx_hi, *bx_lo, *h_hi, *h_lo, *ac_hi, *ac_lo;
    __half *wl_hi, *wl_lo, *wr_hi, *wr_lo, *ws_hi, *ws_lo;
    __half *sl_hi, *sl_lo, *ss_hi, *ss_lo, *srp_hi, *srp_lo, *sy_hi, *sy_lo;
    cudaGetSymbolAddress((void**)&bx_hi, g_boxes_hi);
    cudaGetSymbolAddress((void**)&bx_lo, g_boxes_lo);
    cudaGetSymbolAddress((void**)&h_hi,  g_h_hi);
    cudaGetSymbolAddress((void**)&h_lo,  g_h_lo);
    cudaGetSymbolAddress((void**)&ac_hi, g_acc_hi);
    cudaGetSymbolAddress((void**)&ac_lo, g_acc_lo);
    cudaGetSymbolAddress((void**)&wl_hi, g_Wl_hi);
    cudaGetSymbolAddress((void**)&wl_lo, g_Wl_lo);
    cudaGetSymbolAddress((void**)&wr_hi, g_Wr_hi);
    cudaGetSymbolAddress((void**)&wr_lo, g_Wr_lo);
    cudaGetSymbolAddress((void**)&ws_hi, g_Ws_hi);
    cudaGetSymbolAddress((void**)&ws_lo, g_Ws_lo);
    cudaGetSymbolAddress((void**)&sl_hi, g_Sl_hi);
    cudaGetSymbolAddress((void**)&sl_lo, g_Sl_lo);
    cudaGetSymbolAddress((void**)&ss_hi, g_Ss_hi);
    cudaGetSymbolAddress((void**)&ss_lo, g_Ss_lo);
    cudaGetSymbolAddress((void**)&srp_hi, g_Srp_hi);
    cudaGetSymbolAddress((void**)&srp_lo, g_Srp_lo);
    cudaGetSymbolAddress((void**)&sy_hi, g_sym_hi);
    cudaGetSymbolAddress((void**)&sy_lo, g_sym_lo);

    // 2 stages: BN=128 -> 110592 B; BN=64 -> 73728 B (2 CTAs/SM co-resident)
    const int smem128 = STAGES * (2 * 64 * KROW * 2 + 2 * 128 * KROW * 2);
    const int smem64  = STAGES * (2 * 64 * KROW * 2 + 2 * 64  * KROW * 2);
    cudaFuncSetAttribute(gemm_async<128>,
                         cudaFuncAttributeMaxDynamicSharedMemorySize, smem128);
    cudaFuncSetAttribute(gemm_async<64>,
                         cudaFuncAttributeMaxDynamicSharedMemorySize, smem64);

    dim3 blk(NTHREADS);
    dim3 g1(H_ / 128, B_ / 64);   // h   [2048 x 1024]: 8 x 32 = 256 CTAs
    dim3 g2(F_ / 64,  B_ / 64);   // acc [2048 x 512]:  8 x 32 = 256 CTAs
    const int ldbox = NB_ * F_;

    // prep (3 launches)
    split_weights<<<(5 * WN_) / 256, 256>>>(Wl, Wr, Ws, Sl, Ss);               // 0
    split_pads<<<(H_ * KSYM + B_ * NS_ * KSYM + 255) / 256, 256>>>(Sr, symmetryStacks); // 1
    boxes_kernel<<<(B_ * NB_) / 32, 256>>>(inputStacks, Wb, bb, bx_hi, bx_lo); // 2

    // combine step 0: left = boxes[:,63], right = boxes[:,62]
    gemm_async<128><<<g1, blk, smem128>>>(                                      // 3
        bx_hi + (size_t)63 * F_, bx_lo + (size_t)63 * F_, ldbox,
        wl_hi, wl_lo, F_, F_,
        bx_hi + (size_t)62 * F_, bx_lo + (size_t)62 * F_, ldbox,
        wr_hi, wr_lo, F_, F_,
        bl, nullptr, nullptr, h_hi, h_lo, H_);
    gemm_async<64><<<g2, blk, smem64>>>(                                        // 4
        h_hi, h_lo, H_, ws_hi, ws_lo, H_, H_,
        nullptr, nullptr, 0, nullptr, nullptr, 0, 0,
        bs, nullptr, nullptr, ac_hi, ac_lo, F_);

    // combine steps 1..62 (launch 5 = gemm<128> steady-state, profiled)
    for (int j = 1; j <= 62; j++) {
        gemm_async<128><<<g1, blk, smem128>>>(
            ac_hi, ac_lo, F_,
            wl_hi, wl_lo, F_, F_,
            bx_hi + (size_t)(62 - j) * F_, bx_lo + (size_t)(62 - j) * F_, ldbox,
            wr_hi, wr_lo, F_, F_,
            bl, nullptr, nullptr, h_hi, h_lo, H_);
        gemm_async<64><<<g2, blk, smem64>>>(
            h_hi, h_lo, H_, ws_hi, ws_lo, H_, H_,
            nullptr, nullptr, 0, nullptr, nullptr, 0, 0,
            bs, nullptr, nullptr, ac_hi, ac_lo, F_);
    }

    // symmetry steps: symp = 15 .. 0
    for (int s = 0; s < NS_; s++) {
        int symp = NS_ - 1 - s;
        gemm_async<128><<<g1, blk, smem128>>>(
            ac_hi, ac_lo, F_,
            sl_hi, sl_lo, F_, F_,
            sy_hi + (size_t)symp * KSYM, sy_lo + (size_t)symp * KSYM, NS_ * KSYM,
            srp_hi, srp_lo, KSYM, KSYM,
            sbl, sbr, nullptr, h_hi, h_lo, H_);
        if (s == NS_ - 1) {
            gemm_async<64><<<g2, blk, smem64>>>(
                h_hi, h_lo, H_, ss_hi, ss_lo, H_, H_,
                nullptr, nullptr, 0, nullptr, nullptr, 0, 0,
                sbs, nullptr, out, nullptr, nullptr, F_);
        } else {
            gemm_async<64><<<g2, blk, smem64>>>(
                h_hi, h_lo, H_, ss_hi, ss_lo, H_, H_,
                nullptr, nullptr, 0, nullptr, nullptr, 0, 0,
                sbs, nullptr, nullptr, ac_hi, ac_lo, F_);
        }
    }
}

// round 16
// speedup vs baseline: 1.0638x; 1.0638x over previous
#include <cuda_runtime.h>
#include <cuda_fp16.h>
#include <math.h>
#include <stdint.h>

// Problem constants
#define B_    2048
#define NB_   64
#define NS_   16
#define BOX_  12
#define SYM_  8
#define F_    512
#define H_    1024

#define KC    64          // K per chunk (in halves)
#define KROW  72          // halves per smem row (64 + 8 pad) -> 144B, conflict-free
#define NTHREADS 512
#define STAGES 3
#define KSYM  64          // symmetry operands padded K 8 -> 64
#define NCTAS 128         // persistent grid: all phases tile to exactly 128 CTAs
#define NPHASES 158       // 63 combine steps * 2 + 16 symmetry steps * 2

// ---------------------------------------------------------------------------
// Persistent scratch
// ---------------------------------------------------------------------------
__device__ __align__(16) __half g_boxes_hi[(size_t)B_ * NB_ * F_];
__device__ __align__(16) __half g_boxes_lo[(size_t)B_ * NB_ * F_];
__device__ __align__(16) __half g_h_hi[(size_t)B_ * H_];
__device__ __align__(16) __half g_h_lo[(size_t)B_ * H_];
__device__ __align__(16) __half g_acc_hi[(size_t)B_ * F_];
__device__ __align__(16) __half g_acc_lo[(size_t)B_ * F_];
__device__ __align__(16) __half g_Wl_hi[H_ * F_],  g_Wl_lo[H_ * F_];
__device__ __align__(16) __half g_Wr_hi[H_ * F_],  g_Wr_lo[H_ * F_];
__device__ __align__(16) __half g_Ws_hi[F_ * H_],  g_Ws_lo[F_ * H_];
__device__ __align__(16) __half g_Sl_hi[H_ * F_],  g_Sl_lo[H_ * F_];
__device__ __align__(16) __half g_Ss_hi[F_ * H_],  g_Ss_lo[F_ * H_];
__device__ __align__(16) __half g_Srp_hi[H_ * KSYM], g_Srp_lo[H_ * KSYM];
__device__ __align__(16) __half g_sym_hi[(size_t)B_ * NS_ * KSYM];
__device__ __align__(16) __half g_sym_lo[(size_t)B_ * NS_ * KSYM];
__device__ unsigned int g_bar;   // grid-barrier counter (memset to 0 each replay)

// ---------------------------------------------------------------------------
// helpers
// ---------------------------------------------------------------------------
__device__ __forceinline__ void split1(float x, __half& h, __half& l) {
    h = __float2half_rn(x);
    l = __float2half_rn(x - __half2float(h));
}

__device__ __forceinline__ uint32_t smem_u32_of(const void* p) {
    uint32_t a;
    asm("{ .reg .u64 t; cvta.to.shared.u64 t, %1; cvt.u32.u64 %0, t; }"
        : "=r"(a) : "l"(p));
    return a;
}

#define CP_ASYNC16(d, s) \
    asm volatile("cp.async.cg.shared.global [%0], [%1], 16;" :: "r"(d), "l"(s))
#define CP_COMMIT() asm volatile("cp.async.commit_group;" ::: "memory")
#define CP_WAIT1()  asm volatile("cp.async.wait_group 1;" ::: "memory")
#define CP_WAIT0()  asm volatile("cp.async.wait_group 0;" ::: "memory")

__device__ __forceinline__ void ldsm4(uint32_t* r, uint32_t a) {
    asm volatile("ldmatrix.sync.aligned.m8n8.x4.shared.b16 {%0,%1,%2,%3}, [%4];"
                 : "=r"(r[0]), "=r"(r[1]), "=r"(r[2]), "=r"(r[3]) : "r"(a));
}

__device__ __forceinline__ void mma16816_f32(float* d, const uint32_t* a,
                                             uint32_t b0, uint32_t b1)
{
    asm volatile(
        "mma.sync.aligned.m16n8k16.row.col.f32.f16.f16.f32 "
        "{%0,%1,%2,%3}, {%4,%5,%6,%7}, {%8,%9}, {%0,%1,%2,%3};"
        : "+f"(d[0]), "+f"(d[1]), "+f"(d[2]), "+f"(d[3])
        : "r"(a[0]), "r"(a[1]), "r"(a[2]), "r"(a[3]), "r"(b0), "r"(b1));
}

__device__ __forceinline__ void mma16816_f16(uint32_t* d, const uint32_t* a,
                                             uint32_t b0, uint32_t b1)
{
    asm volatile(
        "mma.sync.aligned.m16n8k16.row.col.f16.f16.f16.f16 "
        "{%0,%1}, {%2,%3,%4,%5}, {%6,%7}, {%0,%1};"
        : "+r"(d[0]), "+r"(d[1])
        : "r"(a[0]), "r"(a[1]), "r"(a[2]), "r"(a[3]), "r"(b0), "r"(b1));
}

// ---------------------------------------------------------------------------
// prep kernels
// ---------------------------------------------------------------------------
#define WN_ (H_ * F_)
__global__ void split_weights(const float* __restrict__ Wl, const float* __restrict__ Wr,
                              const float* __restrict__ Ws, const float* __restrict__ Sl,
                              const float* __restrict__ Ss)
{
    int i = blockIdx.x * 256 + threadIdx.x;
    int seg = i / WN_;
    int j   = i - seg * WN_;
    const float* src;
    __half *hi, *lo;
    switch (seg) {
        case 0: src = Wl; hi = g_Wl_hi; lo = g_Wl_lo; break;
        case 1: src = Wr; hi = g_Wr_hi; lo = g_Wr_lo; break;
        case 2: src = Ws; hi = g_Ws_hi; lo = g_Ws_lo; break;
        case 3: src = Sl; hi = g_Sl_hi; lo = g_Sl_lo; break;
        default: src = Ss; hi = g_Ss_hi; lo = g_Ss_lo; break;
    }
    __half h, l; split1(src[j], h, l);
    hi[j] = h; lo[j] = l;
}

__global__ void split_pads(const float* __restrict__ Sr, const float* __restrict__ sym)
{
    int i = blockIdx.x * 256 + threadIdx.x;
    const int nsr = H_ * KSYM;
    if (i < nsr) {
        int r = i / KSYM, c = i - r * KSYM;
        float x = (c < SYM_) ? Sr[r * SYM_ + c] : 0.f;
        __half h, l; split1(x, h, l);
        g_Srp_hi[i] = h; g_Srp_lo[i] = l;
    } else {
        int k = i - nsr;
        if (k < B_ * NS_ * KSYM) {
            int r = k / KSYM, c = k - r * KSYM;
            float x = (c < SYM_) ? sym[r * SYM_ + c] : 0.f;
            __half h, l; split1(x, h, l);
            g_sym_hi[k] = h; g_sym_lo[k] = l;
        }
    }
}

__global__ void boxes_kernel(const float* __restrict__ in,
                             const float* __restrict__ Wb,
                             const float* __restrict__ bb,
                             __half* __restrict__ out_hi,
                             __half* __restrict__ out_lo)
{
    __shared__ float sW[F_ * BOX_];
    __shared__ float sb[F_];
    __shared__ float sin_[32 * BOX_];
    int tid = threadIdx.x;
    for (int i = tid; i < F_ * BOX_; i += 256) sW[i] = Wb[i];
    for (int i = tid; i < F_; i += 256)        sb[i] = bb[i];
    size_t rowbase = (size_t)blockIdx.x * 32;
    for (int i = tid; i < 32 * BOX_; i += 256) sin_[i] = in[rowbase * BOX_ + i];
    __syncthreads();
    for (int idx = tid; idx < 32 * F_; idx += 256) {
        int r = idx >> 9;
        int c = idx & (F_ - 1);
        float s = sb[c];
        #pragma unroll
        for (int j = 0; j < BOX_; j++)
            s = fmaf(sin_[r * BOX_ + j], sW[c * BOX_ + j], s);
        float t = tanhf(s);
        __half h, l; split1(t, h, l);
        out_hi[(rowbase + r) * F_ + c] = h;
        out_lo[(rowbase + r) * F_ + c] = l;
    }
}

// tiny pad kernels so the persistent GEMM kernel is kernel-launch index 5
__global__ void nop_kernel() {}

// ---------------------------------------------------------------------------
// async copy of R x KC-half tile into smem [R][KROW], 512 threads
// ---------------------------------------------------------------------------
template<int R>
__device__ __forceinline__ void copy_tile(const __half* __restrict__ g, int ldh,
                                          uint32_t sdst, int tid)
{
    constexpr int SEGS = R * 8;
    #pragma unroll
    for (int j = 0; j < SEGS / NTHREADS; j++) {
        int i = tid + NTHREADS * j;
        int row = i >> 3;
        int seg = i & 7;
        CP_ASYNC16(sdst + row * (KROW * 2) + seg * 16,
                   g + (size_t)row * ldh + seg * 8);
    }
}

// ---------------------------------------------------------------------------
// One dual-operand GEMM phase (device function). Identical math to the R11
// kernel: hi*hi -> f32 acc; both cross terms -> one shared f16 acc.
// BM=128, BN template (128 or 64); 512 threads = 16 warps (4m x 4n).
// Chain-dependent A operands arrive via cp.async.cg (L2 path) -> coherent
// across grid-barrier phases within one kernel.
// ---------------------------------------------------------------------------
template<int BN>
__device__ __forceinline__ void run_gemm(
    const __half* __restrict__ A1h, const __half* __restrict__ A1l, int lda1,
    const __half* __restrict__ W1h, const __half* __restrict__ W1l, int ldw1, int K1,
    const __half* __restrict__ A2h, const __half* __restrict__ A2l, int lda2,
    const __half* __restrict__ W2h, const __half* __restrict__ W2l, int ldw2, int K2,
    const float* __restrict__ bias1, const float* __restrict__ bias2,
    float* __restrict__ Cf, __half* __restrict__ Chi, __half* __restrict__ Clo,
    int N, char* smem)
{
    constexpr int BM = 128;
    constexpr int NWARP = BN / 4;
    constexpr int NFRAG = NWARP / 8;
    constexpr int SA_B = BM * (KROW * 2);
    constexpr int SB_B = BN * (KROW * 2);
    constexpr int STAGE_B = 2 * SA_B + 2 * SB_B;

    const uint32_t smem_u = smem_u32_of(smem);
    const int tid  = threadIdx.x;
    const int wid  = tid >> 5;
    const int lane = tid & 31;
    const int wm   = wid & 3;
    const int wn   = wid >> 2;
    const int row0 = (int)(blockIdx.x >> 3) * BM;     // 16 m-tiles
    const int col0 = (int)(blockIdx.x & 7) * BN;      // 8 n-tiles
    const int g    = lane >> 2;
    const int c2   = (lane & 3) * 2;

    float    acc32[2][NFRAG][4];
    uint32_t acc16[2][NFRAG][2];
    #pragma unroll
    for (int mf = 0; mf < 2; mf++)
        #pragma unroll
        for (int nf = 0; nf < NFRAG; nf++) {
            #pragma unroll
            for (int q = 0; q < 4; q++) acc32[mf][nf][q] = 0.f;
            acc16[mf][nf][0] = 0u; acc16[mf][nf][1] = 0u;
        }

    const int n1  = K1 / KC;
    const int n2  = (A2h != nullptr) ? (K2 / KC) : 0;
    const int nch = n1 + n2;

    auto issue = [&](int c) {
        uint32_t sb = smem_u + (uint32_t)(c % STAGES) * STAGE_B;
        const __half *Ah_, *Al_, *Wh_, *Wl_;
        int lda, ldw, k0;
        if (c < n1) { Ah_ = A1h; Al_ = A1l; Wh_ = W1h; Wl_ = W1l;
                      lda = lda1; ldw = ldw1; k0 = c * KC; }
        else        { Ah_ = A2h; Al_ = A2l; Wh_ = W2h; Wl_ = W2l;
                      lda = lda2; ldw = ldw2; k0 = (c - n1) * KC; }
        copy_tile<BM>(Ah_ + (size_t)row0 * lda + k0, lda, sb, tid);
        copy_tile<BM>(Al_ + (size_t)row0 * lda + k0, lda, sb + SA_B, tid);
        copy_tile<BN>(Wh_ + (size_t)col0 * ldw + k0, ldw, sb + 2 * SA_B, tid);
        copy_tile<BN>(Wl_ + (size_t)col0 * ldw + k0, ldw, sb + 2 * SA_B + SB_B, tid);
        CP_COMMIT();
    };

    const int npro = (nch < STAGES - 1) ? nch : (STAGES - 1);
    for (int s = 0; s < npro; s++) issue(s);

    for (int c = 0; c < nch; c++) {
        if (c + 1 < nch) { CP_WAIT1(); } else { CP_WAIT0(); }
        __syncthreads();
        if (c + STAGES - 1 < nch) issue(c + STAGES - 1);

        const uint32_t sb = smem_u + (uint32_t)(c % STAGES) * STAGE_B;
        const uint32_t aAhi = sb;
        const uint32_t aAlo = sb + SA_B;
        const uint32_t aBhi = sb + 2 * SA_B;
        const uint32_t aBlo = sb + 2 * SA_B + SB_B;

        #pragma unroll
        for (int kf = 0; kf < 4; kf++) {
            uint32_t Af[2][4], Alf[2][4];
            const int aoff = ((wm * 32 + (lane & 15)) * KROW
                              + kf * 16 + (lane >> 4) * 8) * 2;
            #pragma unroll
            for (int mf = 0; mf < 2; mf++) {
                ldsm4(Af[mf],  aAhi + aoff + mf * 16 * KROW * 2);
                ldsm4(Alf[mf], aAlo + aoff + mf * 16 * KROW * 2);
            }
            const int boff = ((wn * NWARP + (lane >> 4) * 8 + (lane & 7)) * KROW
                              + kf * 16 + ((lane >> 3) & 1) * 8) * 2;
            #pragma unroll
            for (int nfp = 0; nfp < NFRAG / 2; nfp++) {
                uint32_t Bh[4], Bl[4];
                ldsm4(Bh, aBhi + boff + nfp * 16 * KROW * 2);
                ldsm4(Bl, aBlo + boff + nfp * 16 * KROW * 2);
                #pragma unroll
                for (int mf = 0; mf < 2; mf++) {
                    mma16816_f32(acc32[mf][2 * nfp],     Af[mf],  Bh[0], Bh[1]);
                    mma16816_f32(acc32[mf][2 * nfp + 1], Af[mf],  Bh[2], Bh[3]);
                    mma16816_f16(acc16[mf][2 * nfp],     Af[mf],  Bl[0], Bl[1]);
                    mma16816_f16(acc16[mf][2 * nfp],     Alf[mf], Bh[0], Bh[1]);
                    mma16816_f16(acc16[mf][2 * nfp + 1], Af[mf],  Bl[2], Bl[3]);
                    mma16816_f16(acc16[mf][2 * nfp + 1], Alf[mf], Bh[2], Bh[3]);
                }
            }
        }
    }

    // Epilogue: merge f16 cross-sums, bias + tanh
    #pragma unroll
    for (int mf = 0; mf < 2; mf++) {
        const int r = row0 + wm * 32 + mf * 16 + g;
        #pragma unroll
        for (int nf = 0; nf < NFRAG; nf++) {
            const int cc = col0 + wn * NWARP + nf * 8 + c2;
            __half2 x0 = *reinterpret_cast<__half2*>(&acc16[mf][nf][0]);
            __half2 x1 = *reinterpret_cast<__half2*>(&acc16[mf][nf][1]);
            float b0 = bias1[cc + 0] + (bias2 ? bias2[cc + 0] : 0.f);
            float b1 = bias1[cc + 1] + (bias2 ? bias2[cc + 1] : 0.f);
            float t00 = tanhf(acc32[mf][nf][0] + __low2float(x0)  + b0);
            float t01 = tanhf(acc32[mf][nf][1] + __high2float(x0) + b1);
            float t10 = tanhf(acc32[mf][nf][2] + __low2float(x1)  + b0);
            float t11 = tanhf(acc32[mf][nf][3] + __high2float(x1) + b1);
            if (Cf) {
                *reinterpret_cast<float2*>(Cf + (size_t)r * N + cc)       = make_float2(t00, t01);
                *reinterpret_cast<float2*>(Cf + (size_t)(r + 8) * N + cc) = make_float2(t10, t11);
            } else {
                __half h00, l00, h01, l01, h10, l10, h11, l11;
                split1(t00, h00, l00); split1(t01, h01, l01);
                split1(t10, h10, l10); split1(t11, h11, l11);
                *reinterpret_cast<__half2*>(Chi + (size_t)r * N + cc)       = __halves2half2(h00, h01);
                *reinterpret_cast<__half2*>(Clo + (size_t)r * N + cc)       = __halves2half2(l00, l01);
                *reinterpret_cast<__half2*>(Chi + (size_t)(r + 8) * N + cc) = __halves2half2(h10, h11);
                *reinterpret_cast<__half2*>(Clo + (size_t)(r + 8) * N + cc) = __halves2half2(l10, l11);
            }
        }
    }
}

// ---------------------------------------------------------------------------
// Grid barrier: monotonic counter, release/acquire via threadfence.
// All NCTAS CTAs are co-resident (1 CTA/SM, 128 <= 148), so spinning is safe.
// ---------------------------------------------------------------------------
__device__ __forceinline__ void grid_sync(unsigned int target)
{
    __syncthreads();
    if (threadIdx.x == 0) {
        __threadfence();
        atomicAdd(&g_bar, 1u);
        volatile unsigned int* p = &g_bar;
        while (*p < target) { }
        __threadfence();
    }
    __syncthreads();
}

// ---------------------------------------------------------------------------
// Persistent chain kernel: all 158 GEMM phases with grid barriers between.
// Phase 2j   (j=0..62):  h  = tanh(Wl*left + Wr*boxes[62-j] + bl)     BN=128
// Phase 2j+1 (j=0..62):  acc= tanh(Ws*h + bs)                         BN=64
// Phase 126+2s (s=0..15):h  = tanh(Sl*acc + Srp*sym[15-s] + sbl+sbr)  BN=128
// Phase 127+2s:          acc/out = tanh(Ss*h + sbs)                   BN=64
// ---------------------------------------------------------------------------
__global__ void __launch_bounds__(NTHREADS, 1)
chain_kernel(const float* __restrict__ bl, const float* __restrict__ bs,
             const float* __restrict__ sbl, const float* __restrict__ sbr,
             const float* __restrict__ sbs,
             float* __restrict__ out)
{
    extern __shared__ __align__(16) char smem[];
    const int ldbox = NB_ * F_;

    unsigned int target = (unsigned int)gridDim.x;
    for (int ph = 0; ph < NPHASES; ph++) {
        if (ph < 126) {
            int j = ph >> 1;
            if (!(ph & 1)) {
                const __half* a1h = (j == 0) ? g_boxes_hi + (size_t)63 * F_ : g_acc_hi;
                const __half* a1l = (j == 0) ? g_boxes_lo + (size_t)63 * F_ : g_acc_lo;
                int lda1 = (j == 0) ? ldbox : F_;
                run_gemm<128>(a1h, a1l, lda1,
                              g_Wl_hi, g_Wl_lo, F_, F_,
                              g_boxes_hi + (size_t)(62 - j) * F_,
                              g_boxes_lo + (size_t)(62 - j) * F_, ldbox,
                              g_Wr_hi, g_Wr_lo, F_, F_,
                              bl, nullptr,
                              nullptr, g_h_hi, g_h_lo, H_, smem);
            } else {
                run_gemm<64>(g_h_hi, g_h_lo, H_,
                             g_Ws_hi, g_Ws_lo, H_, H_,
                             nullptr, nullptr, 0, nullptr, nullptr, 0, 0,
                             bs, nullptr,
                             nullptr, g_acc_hi, g_acc_lo, F_, smem);
            }
        } else {
            int s = (ph - 126) >> 1;
            int symp = NS_ - 1 - s;
            if (!(ph & 1)) {
                run_gemm<128>(g_acc_hi, g_acc_lo, F_,
                              g_Sl_hi, g_Sl_lo, F_, F_,
                              g_sym_hi + (size_t)symp * KSYM,
                              g_sym_lo + (size_t)symp * KSYM, NS_ * KSYM,
                              g_Srp_hi, g_Srp_lo, KSYM, KSYM,
                              sbl, sbr,
                              nullptr, g_h_hi, g_h_lo, H_, smem);
            } else if (s < NS_ - 1) {
                run_gemm<64>(g_h_hi, g_h_lo, H_,
                             g_Ss_hi, g_Ss_lo, H_, H_,
                             nullptr, nullptr, 0, nullptr, nullptr, 0, 0,
                             sbs, nullptr,
                             nullptr, g_acc_hi, g_acc_lo, F_, smem);
            } else {
                run_gemm<64>(g_h_hi, g_h_lo, H_,
                             g_Ss_hi, g_Ss_lo, H_, H_,
                             nullptr, nullptr, 0, nullptr, nullptr, 0, 0,
                             sbs, nullptr,
                             out, nullptr, nullptr, F_, smem);
            }
        }
        if (ph + 1 < NPHASES) grid_sync(target);
        target += (unsigned int)gridDim.x;
    }
}

// ---------------------------------------------------------------------------
// kernel_launch
// ---------------------------------------------------------------------------
extern "C" void kernel_launch(void* const* d_in, const int* in_sizes, int n_in,
                              void* d_out, int out_size)
{
    const float* inputStacks    = (const float*)d_in[0];
    const float* symmetryStacks = (const float*)d_in[1];
    const float* Wb  = (const float*)d_in[3];
    const float* bb  = (const float*)d_in[4];
    const float* Wl  = (const float*)d_in[5];
    const float* bl  = (const float*)d_in[6];
    const float* Wr  = (const float*)d_in[7];
    const float* Ws  = (const float*)d_in[8];
    const float* bs  = (const float*)d_in[9];
    const float* Sl  = (const float*)d_in[10];
    const float* sbl = (const float*)d_in[11];
    const float* Sr  = (const float*)d_in[12];
    const float* sbr = (const float*)d_in[13];
    const float* Ss  = (const float*)d_in[14];
    const float* sbs = (const float*)d_in[15];
    float* out = (float*)d_out;

    __half *bx_hi, *bx_lo;
    unsigned int* barp;
    cudaGetSymbolAddress((void**)&bx_hi, g_boxes_hi);
    cudaGetSymbolAddress((void**)&bx_lo, g_boxes_lo);
    cudaGetSymbolAddress((void**)&barp,  g_bar);

    // persistent kernel smem: BN=128 stage set = 3 * 4 * (128*144) = 221184 B
    const int smemP = STAGES * 4 * 128 * (KROW * 2);
    cudaFuncSetAttribute(chain_kernel,
                         cudaFuncAttributeMaxDynamicSharedMemorySize, smemP);

    // reset grid barrier (memset node, not a kernel)
    cudaMemsetAsync(barp, 0, sizeof(unsigned int));

    // kernels 0..4 (so chain_kernel is kernel index 5 for ncu -s 5 -c 1)
    split_weights<<<(5 * WN_) / 256, 256>>>(Wl, Wr, Ws, Sl, Ss);               // 0
    split_pads<<<(H_ * KSYM + B_ * NS_ * KSYM + 255) / 256, 256>>>(Sr, symmetryStacks); // 1
    boxes_kernel<<<(B_ * NB_) / 32, 256>>>(inputStacks, Wb, bb, bx_hi, bx_lo); // 2
    nop_kernel<<<1, 32>>>();                                                    // 3
    nop_kernel<<<1, 32>>>();                                                    // 4

    // 5: the whole 158-GEMM chain in one persistent launch
    chain_kernel<<<NCTAS, NTHREADS, smemP>>>(bl, bs, sbl, sbr, sbs, out);
}

// round 17
// speedup vs baseline: 1.0831x; 1.0182x over previous
#include <cuda_runtime.h>
#include <cuda_fp16.h>
#include <math.h>
#include <stdint.h>

// Problem constants
#define B_    2048
#define NB_   64
#define NS_   16
#define BOX_  12
#define SYM_  8
#define F_    512
#define H_    1024

#define KC    64          // K per chunk (in halves)
#define KROW  72          // halves per smem row (64 + 8 pad) -> 144B, conflict-free
#define NTHREADS 512
#define STAGES 3
#define KSYM  64          // symmetry operands padded K 8 -> 64
#define NCTAS 128         // persistent grid: all phases tile to exactly 128 CTAs
#define NPHASES 158       // 63 combine steps * 2 + 16 symmetry steps * 2
#define MBLKS 16          // m-blocks of 128 rows (same for both phase shapes)
#define NTILES_PER_MBLK 8 // n-tiles per m-block (1024/128 and 512/64)

// ---------------------------------------------------------------------------
// Persistent scratch
// ---------------------------------------------------------------------------
__device__ __align__(16) __half g_boxes_hi[(size_t)B_ * NB_ * F_];
__device__ __align__(16) __half g_boxes_lo[(size_t)B_ * NB_ * F_];
__device__ __align__(16) __half g_h_hi[(size_t)B_ * H_];
__device__ __align__(16) __half g_h_lo[(size_t)B_ * H_];
__device__ __align__(16) __half g_acc_hi[(size_t)B_ * F_];
__device__ __align__(16) __half g_acc_lo[(size_t)B_ * F_];
__device__ __align__(16) __half g_Wl_hi[H_ * F_],  g_Wl_lo[H_ * F_];
__device__ __align__(16) __half g_Wr_hi[H_ * F_],  g_Wr_lo[H_ * F_];
__device__ __align__(16) __half g_Ws_hi[F_ * H_],  g_Ws_lo[F_ * H_];
__device__ __align__(16) __half g_Sl_hi[H_ * F_],  g_Sl_lo[H_ * F_];
__device__ __align__(16) __half g_Ss_hi[F_ * H_],  g_Ss_lo[F_ * H_];
__device__ __align__(16) __half g_Srp_hi[H_ * KSYM], g_Srp_lo[H_ * KSYM];
__device__ __align__(16) __half g_sym_hi[(size_t)B_ * NS_ * KSYM];
__device__ __align__(16) __half g_sym_lo[(size_t)B_ * NS_ * KSYM];
// per-(phase, m-block) completion counters (memset to 0 each replay)
__device__ unsigned int g_cnt[NPHASES][MBLKS];

// ---------------------------------------------------------------------------
// helpers
// ---------------------------------------------------------------------------
__device__ __forceinline__ void split1(float x, __half& h, __half& l) {
    h = __float2half_rn(x);
    l = __float2half_rn(x - __half2float(h));
}

__device__ __forceinline__ uint32_t smem_u32_of(const void* p) {
    uint32_t a;
    asm("{ .reg .u64 t; cvta.to.shared.u64 t, %1; cvt.u32.u64 %0, t; }"
        : "=r"(a) : "l"(p));
    return a;
}

#define CP_ASYNC16(d, s) \
    asm volatile("cp.async.cg.shared.global [%0], [%1], 16;" :: "r"(d), "l"(s))
#define CP_COMMIT() asm volatile("cp.async.commit_group;" ::: "memory")
#define CP_WAIT1()  asm volatile("cp.async.wait_group 1;" ::: "memory")
#define CP_WAIT0()  asm volatile("cp.async.wait_group 0;" ::: "memory")

__device__ __forceinline__ void ldsm4(uint32_t* r, uint32_t a) {
    asm volatile("ldmatrix.sync.aligned.m8n8.x4.shared.b16 {%0,%1,%2,%3}, [%4];"
                 : "=r"(r[0]), "=r"(r[1]), "=r"(r[2]), "=r"(r[3]) : "r"(a));
}

__device__ __forceinline__ void mma16816_f32(float* d, const uint32_t* a,
                                             uint32_t b0, uint32_t b1)
{
    asm volatile(
        "mma.sync.aligned.m16n8k16.row.col.f32.f16.f16.f32 "
        "{%0,%1,%2,%3}, {%4,%5,%6,%7}, {%8,%9}, {%0,%1,%2,%3};"
        : "+f"(d[0]), "+f"(d[1]), "+f"(d[2]), "+f"(d[3])
        : "r"(a[0]), "r"(a[1]), "r"(a[2]), "r"(a[3]), "r"(b0), "r"(b1));
}

__device__ __forceinline__ void mma16816_f16(uint32_t* d, const uint32_t* a,
                                             uint32_t b0, uint32_t b1)
{
    asm volatile(
        "mma.sync.aligned.m16n8k16.row.col.f16.f16.f16.f16 "
        "{%0,%1}, {%2,%3,%4,%5}, {%6,%7}, {%0,%1};"
        : "+r"(d[0]), "+r"(d[1])
        : "r"(a[0]), "r"(a[1]), "r"(a[2]), "r"(a[3]), "r"(b0), "r"(b1));
}

// ---------------------------------------------------------------------------
// prep kernels
// ---------------------------------------------------------------------------
#define WN_ (H_ * F_)
__global__ void split_weights(const float* __restrict__ Wl, const float* __restrict__ Wr,
                              const float* __restrict__ Ws, const float* __restrict__ Sl,
                              const float* __restrict__ Ss)
{
    int i = blockIdx.x * 256 + threadIdx.x;
    int seg = i / WN_;
    int j   = i - seg * WN_;
    const float* src;
    __half *hi, *lo;
    switch (seg) {
        case 0: src = Wl; hi = g_Wl_hi; lo = g_Wl_lo; break;
        case 1: src = Wr; hi = g_Wr_hi; lo = g_Wr_lo; break;
        case 2: src = Ws; hi = g_Ws_hi; lo = g_Ws_lo; break;
        case 3: src = Sl; hi = g_Sl_hi; lo = g_Sl_lo; break;
        default: src = Ss; hi = g_Ss_hi; lo = g_Ss_lo; break;
    }
    __half h, l; split1(src[j], h, l);
    hi[j] = h; lo[j] = l;
}

__global__ void split_pads(const float* __restrict__ Sr, const float* __restrict__ sym)
{
    int i = blockIdx.x * 256 + threadIdx.x;
    const int nsr = H_ * KSYM;
    if (i < nsr) {
        int r = i / KSYM, c = i - r * KSYM;
        float x = (c < SYM_) ? Sr[r * SYM_ + c] : 0.f;
        __half h, l; split1(x, h, l);
        g_Srp_hi[i] = h; g_Srp_lo[i] = l;
    } else {
        int k = i - nsr;
        if (k < B_ * NS_ * KSYM) {
            int r = k / KSYM, c = k - r * KSYM;
            float x = (c < SYM_) ? sym[r * SYM_ + c] : 0.f;
            __half h, l; split1(x, h, l);
            g_sym_hi[k] = h; g_sym_lo[k] = l;
        }
    }
}

__global__ void boxes_kernel(const float* __restrict__ in,
                             const float* __restrict__ Wb,
                             const float* __restrict__ bb,
                             __half* __restrict__ out_hi,
                             __half* __restrict__ out_lo)
{
    __shared__ float sW[F_ * BOX_];
    __shared__ float sb[F_];
    __shared__ float sin_[32 * BOX_];
    int tid = threadIdx.x;
    for (int i = tid; i < F_ * BOX_; i += 256) sW[i] = Wb[i];
    for (int i = tid; i < F_; i += 256)        sb[i] = bb[i];
    size_t rowbase = (size_t)blockIdx.x * 32;
    for (int i = tid; i < 32 * BOX_; i += 256) sin_[i] = in[rowbase * BOX_ + i];
    __syncthreads();
    for (int idx = tid; idx < 32 * F_; idx += 256) {
        int r = idx >> 9;
        int c = idx & (F_ - 1);
        float s = sb[c];
        #pragma unroll
        for (int j = 0; j < BOX_; j++)
            s = fmaf(sin_[r * BOX_ + j], sW[c * BOX_ + j], s);
        float t = tanhf(s);
        __half h, l; split1(t, h, l);
        out_hi[(rowbase + r) * F_ + c] = h;
        out_lo[(rowbase + r) * F_ + c] = l;
    }
}

__global__ void nop_kernel() {}

// ---------------------------------------------------------------------------
// async copy of R x KC-half tile into smem [R][KROW], 512 threads
// ---------------------------------------------------------------------------
template<int R>
__device__ __forceinline__ void copy_tile(const __half* __restrict__ g, int ldh,
                                          uint32_t sdst, int tid)
{
    constexpr int SEGS = R * 8;
    #pragma unroll
    for (int j = 0; j < SEGS / NTHREADS; j++) {
        int i = tid + NTHREADS * j;
        int row = i >> 3;
        int seg = i & 7;
        CP_ASYNC16(sdst + row * (KROW * 2) + seg * 16,
                   g + (size_t)row * ldh + seg * 8);
    }
}

// ---------------------------------------------------------------------------
// One dual-operand GEMM phase (device function), identical math to R11:
// hi*hi -> f32 acc; both cross terms -> one shared f16 acc.
// BM=128, BN template (128 or 64); 512 threads = 16 warps (4m x 4n).
// Chain-dependent operands load via cp.async.cg (L2 path, coherent in-kernel).
// ---------------------------------------------------------------------------
template<int BN>
__device__ __forceinline__ void run_gemm(
    const __half* __restrict__ A1h, const __half* __restrict__ A1l, int lda1,
    const __half* __restrict__ W1h, const __half* __restrict__ W1l, int ldw1, int K1,
    const __half* __restrict__ A2h, const __half* __restrict__ A2l, int lda2,
    const __half* __restrict__ W2h, const __half* __restrict__ W2l, int ldw2, int K2,
    const float* __restrict__ bias1, const float* __restrict__ bias2,
    float* __restrict__ Cf, __half* __restrict__ Chi, __half* __restrict__ Clo,
    int N, char* smem)
{
    constexpr int BM = 128;
    constexpr int NWARP = BN / 4;
    constexpr int NFRAG = NWARP / 8;
    constexpr int SA_B = BM * (KROW * 2);
    constexpr int SB_B = BN * (KROW * 2);
    constexpr int STAGE_B = 2 * SA_B + 2 * SB_B;

    const uint32_t smem_u = smem_u32_of(smem);
    const int tid  = threadIdx.x;
    const int wid  = tid >> 5;
    const int lane = tid & 31;
    const int wm   = wid & 3;
    const int wn   = wid >> 2;
    const int row0 = (int)(blockIdx.x >> 3) * BM;     // 16 m-blocks
    const int col0 = (int)(blockIdx.x & 7) * BN;      // 8 n-tiles
    const int g    = lane >> 2;
    const int c2   = (lane & 3) * 2;

    float    acc32[2][NFRAG][4];
    uint32_t acc16[2][NFRAG][2];
    #pragma unroll
    for (int mf = 0; mf < 2; mf++)
        #pragma unroll
        for (int nf = 0; nf < NFRAG; nf++) {
            #pragma unroll
            for (int q = 0; q < 4; q++) acc32[mf][nf][q] = 0.f;
            acc16[mf][nf][0] = 0u; acc16[mf][nf][1] = 0u;
        }

    const int n1  = K1 / KC;
    const int n2  = (A2h != nullptr) ? (K2 / KC) : 0;
    const int nch = n1 + n2;

    auto issue = [&](int c) {
        uint32_t sb = smem_u + (uint32_t)(c % STAGES) * STAGE_B;
        const __half *Ah_, *Al_, *Wh_, *Wl_;
        int lda, ldw, k0;
        if (c < n1) { Ah_ = A1h; Al_ = A1l; Wh_ = W1h; Wl_ = W1l;
                      lda = lda1; ldw = ldw1; k0 = c * KC; }
        else        { Ah_ = A2h; Al_ = A2l; Wh_ = W2h; Wl_ = W2l;
                      lda = lda2; ldw = ldw2; k0 = (c - n1) * KC; }
        copy_tile<BM>(Ah_ + (size_t)row0 * lda + k0, lda, sb, tid);
        copy_tile<BM>(Al_ + (size_t)row0 * lda + k0, lda, sb + SA_B, tid);
        copy_tile<BN>(Wh_ + (size_t)col0 * ldw + k0, ldw, sb + 2 * SA_B, tid);
        copy_tile<BN>(Wl_ + (size_t)col0 * ldw + k0, ldw, sb + 2 * SA_B + SB_B, tid);
        CP_COMMIT();
    };

    const int npro = (nch < STAGES - 1) ? nch : (STAGES - 1);
    for (int s = 0; s < npro; s++) issue(s);

    for (int c = 0; c < nch; c++) {
        if (c + 1 < nch) { CP_WAIT1(); } else { CP_WAIT0(); }
        __syncthreads();
        if (c + STAGES - 1 < nch) issue(c + STAGES - 1);

        const uint32_t sb = smem_u + (uint32_t)(c % STAGES) * STAGE_B;
        const uint32_t aAhi = sb;
        const uint32_t aAlo = sb + SA_B;
        const uint32_t aBhi = sb + 2 * SA_B;
        const uint32_t aBlo = sb + 2 * SA_B + SB_B;

        #pragma unroll
        for (int kf = 0; kf < 4; kf++) {
            uint32_t Af[2][4], Alf[2][4];
            const int aoff = ((wm * 32 + (lane & 15)) * KROW
                              + kf * 16 + (lane >> 4) * 8) * 2;
            #pragma unroll
            for (int mf = 0; mf < 2; mf++) {
                ldsm4(Af[mf],  aAhi + aoff + mf * 16 * KROW * 2);
                ldsm4(Alf[mf], aAlo + aoff + mf * 16 * KROW * 2);
            }
            const int boff = ((wn * NWARP + (lane >> 4) * 8 + (lane & 7)) * KROW
                              + kf * 16 + ((lane >> 3) & 1) * 8) * 2;
            #pragma unroll
            for (int nfp = 0; nfp < NFRAG / 2; nfp++) {
                uint32_t Bh[4], Bl[4];
                ldsm4(Bh, aBhi + boff + nfp * 16 * KROW * 2);
                ldsm4(Bl, aBlo + boff + nfp * 16 * KROW * 2);
                #pragma unroll
                for (int mf = 0; mf < 2; mf++) {
                    mma16816_f32(acc32[mf][2 * nfp],     Af[mf],  Bh[0], Bh[1]);
                    mma16816_f32(acc32[mf][2 * nfp + 1], Af[mf],  Bh[2], Bh[3]);
                    mma16816_f16(acc16[mf][2 * nfp],     Af[mf],  Bl[0], Bl[1]);
                    mma16816_f16(acc16[mf][2 * nfp],     Alf[mf], Bh[0], Bh[1]);
                    mma16816_f16(acc16[mf][2 * nfp + 1], Af[mf],  Bl[2], Bl[3]);
                    mma16816_f16(acc16[mf][2 * nfp + 1], Alf[mf], Bh[2], Bh[3]);
                }
            }
        }
    }

    // Epilogue: merge f16 cross-sums, bias + tanh
    #pragma unroll
    for (int mf = 0; mf < 2; mf++) {
        const int r = row0 + wm * 32 + mf * 16 + g;
        #pragma unroll
        for (int nf = 0; nf < NFRAG; nf++) {
            const int cc = col0 + wn * NWARP + nf * 8 + c2;
            __half2 x0 = *reinterpret_cast<__half2*>(&acc16[mf][nf][0]);
            __half2 x1 = *reinterpret_cast<__half2*>(&acc16[mf][nf][1]);
            float b0 = bias1[cc + 0] + (bias2 ? bias2[cc + 0] : 0.f);
            float b1 = bias1[cc + 1] + (bias2 ? bias2[cc + 1] : 0.f);
            float t00 = tanhf(acc32[mf][nf][0] + __low2float(x0)  + b0);
            float t01 = tanhf(acc32[mf][nf][1] + __high2float(x0) + b1);
            float t10 = tanhf(acc32[mf][nf][2] + __low2float(x1)  + b0);
            float t11 = tanhf(acc32[mf][nf][3] + __high2float(x1) + b1);
            if (Cf) {
                *reinterpret_cast<float2*>(Cf + (size_t)r * N + cc)       = make_float2(t00, t01);
                *reinterpret_cast<float2*>(Cf + (size_t)(r + 8) * N + cc) = make_float2(t10, t11);
            } else {
                __half h00, l00, h01, l01, h10, l10, h11, l11;
                split1(t00, h00, l00); split1(t01, h01, l01);
                split1(t10, h10, l10); split1(t11, h11, l11);
                *reinterpret_cast<__half2*>(Chi + (size_t)r * N + cc)       = __halves2half2(h00, h01);
                *reinterpret_cast<__half2*>(Clo + (size_t)r * N + cc)       = __halves2half2(l00, l01);
                *reinterpret_cast<__half2*>(Chi + (size_t)(r + 8) * N + cc) = __halves2half2(h10, h11);
                *reinterpret_cast<__half2*>(Clo + (size_t)(r + 8) * N + cc) = __halves2half2(l10, l11);
            }
        }
    }
}

// ---------------------------------------------------------------------------
// Persistent chain kernel with fine-grained per-m-block dependency sync.
// Consumer CTA (mblk, n) of phase p waits only for the 8 producer CTAs
// (mblk, *) of phase p-1. Covers RAW and WAR hazards (see analysis).
// ---------------------------------------------------------------------------
__global__ void __launch_bounds__(NTHREADS, 1)
chain_kernel(const float* __restrict__ bl, const float* __restrict__ bs,
             const float* __restrict__ sbl, const float* __restrict__ sbr,
             const float* __restrict__ sbs,
             float* __restrict__ out)
{
    extern __shared__ __align__(16) char smem[];
    const int ldbox = NB_ * F_;
    const int mblk  = (int)(blockIdx.x >> 3);

    for (int ph = 0; ph < NPHASES; ph++) {
        // wait for previous phase's producers of this m-block
        if (ph > 0) {
            if (threadIdx.x == 0) {
                volatile unsigned int* p = &g_cnt[ph - 1][mblk];
                while (*p < (unsigned int)NTILES_PER_MBLK) { }
                __threadfence();
            }
            __syncthreads();
        }

        if (ph < 126) {
            int j = ph >> 1;
            if (!(ph & 1)) {
                const __half* a1h = (j == 0) ? g_boxes_hi + (size_t)63 * F_ : g_acc_hi;
                const __half* a1l = (j == 0) ? g_boxes_lo + (size_t)63 * F_ : g_acc_lo;
                int lda1 = (j == 0) ? ldbox : F_;
                run_gemm<128>(a1h, a1l, lda1,
                              g_Wl_hi, g_Wl_lo, F_, F_,
                              g_boxes_hi + (size_t)(62 - j) * F_,
                              g_boxes_lo + (size_t)(62 - j) * F_, ldbox,
                              g_Wr_hi, g_Wr_lo, F_, F_,
                              bl, nullptr,
                              nullptr, g_h_hi, g_h_lo, H_, smem);
            } else {
                run_gemm<64>(g_h_hi, g_h_lo, H_,
                             g_Ws_hi, g_Ws_lo, H_, H_,
                             nullptr, nullptr, 0, nullptr, nullptr, 0, 0,
                             bs, nullptr,
                             nullptr, g_acc_hi, g_acc_lo, F_, smem);
            }
        } else {
            int s = (ph - 126) >> 1;
            int symp = NS_ - 1 - s;
            if (!(ph & 1)) {
                run_gemm<128>(g_acc_hi, g_acc_lo, F_,
                              g_Sl_hi, g_Sl_lo, F_, F_,
                              g_sym_hi + (size_t)symp * KSYM,
                              g_sym_lo + (size_t)symp * KSYM, NS_ * KSYM,
                              g_Srp_hi, g_Srp_lo, KSYM, KSYM,
                              sbl, sbr,
                              nullptr, g_h_hi, g_h_lo, H_, smem);
            } else if (s < NS_ - 1) {
                run_gemm<64>(g_h_hi, g_h_lo, H_,
                             g_Ss_hi, g_Ss_lo, H_, H_,
                             nullptr, nullptr, 0, nullptr, nullptr, 0, 0,
                             sbs, nullptr,
                             nullptr, g_acc_hi, g_acc_lo, F_, smem);
            } else {
                run_gemm<64>(g_h_hi, g_h_lo, H_,
                             g_Ss_hi, g_Ss_lo, H_, H_,
                             nullptr, nullptr, 0, nullptr, nullptr, 0, 0,
                             sbs, nullptr,
                             out, nullptr, nullptr, F_, smem);
            }
        }

        // signal completion of this tile (release: fence all threads' stores,
        // block-order via syncthreads, then one atomic)
        if (ph + 1 < NPHASES) {
            __threadfence();
            __syncthreads();
            if (threadIdx.x == 0) atomicAdd(&g_cnt[ph][mblk], 1u);
        }
    }
}

// ---------------------------------------------------------------------------
// kernel_launch
// ---------------------------------------------------------------------------
extern "C" void kernel_launch(void* const* d_in, const int* in_sizes, int n_in,
                              void* d_out, int out_size)
{
    const float* inputStacks    = (const float*)d_in[0];
    const float* symmetryStacks = (const float*)d_in[1];
    const float* Wb  = (const float*)d_in[3];
    const float* bb  = (const float*)d_in[4];
    const float* Wl  = (const float*)d_in[5];
    const float* bl  = (const float*)d_in[6];
    const float* Wr  = (const float*)d_in[7];
    const float* Ws  = (const float*)d_in[8];
    const float* bs  = (const float*)d_in[9];
    const float* Sl  = (const float*)d_in[10];
    const float* sbl = (const float*)d_in[11];
    const float* Sr  = (const float*)d_in[12];
    const float* sbr = (const float*)d_in[13];
    const float* Ss  = (const float*)d_in[14];
    const float* sbs = (const float*)d_in[15];
    float* out = (float*)d_out;

    __half *bx_hi, *bx_lo;
    unsigned int* cntp;
    cudaGetSymbolAddress((void**)&bx_hi, g_boxes_hi);
    cudaGetSymbolAddress((void**)&bx_lo, g_boxes_lo);
    cudaGetSymbolAddress((void**)&cntp,  g_cnt);

    const int smemP = STAGES * 4 * 128 * (KROW * 2);   // 221184 B
    cudaFuncSetAttribute(chain_kernel,
                         cudaFuncAttributeMaxDynamicSharedMemorySize, smemP);

    // reset dependency counters (replayed graph node)
    cudaMemsetAsync(cntp, 0, sizeof(unsigned int) * NPHASES * MBLKS);

    // node order: memset(0), split(1), pads(2), boxes(3), nop(4), chain(5)
    split_weights<<<(5 * WN_) / 256, 256>>>(Wl, Wr, Ws, Sl, Ss);
    split_pads<<<(H_ * KSYM + B_ * NS_ * KSYM + 255) / 256, 256>>>(Sr, symmetryStacks);
    boxes_kernel<<<(B_ * NB_) / 32, 256>>>(inputStacks, Wb, bb, bx_hi, bx_lo);
    nop_kernel<<<1, 32>>>();

    chain_kernel<<<NCTAS, NTHREADS, smemP>>>(bl, bs, sbl, sbr, sbs, out);
}